// round 1
// baseline (speedup 1.0000x reference)
#include <cuda_runtime.h>

// Problem dims
#define E_  8
#define B_  4096
#define L_  512
#define H1_ 1024
#define H2_ 512
#define C_  40

// Scratch (device globals: allocation-free per harness rules)
__device__ float g_h1[B_ * H1_];          // sorted-order layer1 activations
__device__ float g_h2[B_ * H2_];          // sorted-order layer2 activations
__device__ int   g_perm[B_];
__device__ int   g_off[E_ + 1];
__device__ int   g_cnt[E_];
__device__ int   g_pos[E_];

// ---------------- counting sort by expert ----------------
__global__ void k_init() {
    int t = threadIdx.x;
    if (t < E_) { g_cnt[t] = 0; g_pos[t] = 0; }
}

__global__ void k_hist(const int* __restrict__ label) {
    int b = blockIdx.x * blockDim.x + threadIdx.x;
    if (b < B_) atomicAdd(&g_cnt[label[b]], 1);
}

__global__ void k_scan() {
    int s = 0;
    g_off[0] = 0;
    for (int e = 0; e < E_; e++) { s += g_cnt[e]; g_off[e + 1] = s; }
}

__global__ void k_scatter(const int* __restrict__ label) {
    int b = blockIdx.x * blockDim.x + threadIdx.x;
    if (b < B_) {
        int e = label[b];
        int p = atomicAdd(&g_pos[e], 1);
        g_perm[g_off[e] + p] = b;
    }
}

// ---------------- grouped SGEMM, fused bias+ELU ----------------
// LAYER==1: A = gathered concat([x_p, x_s]) rows, Out = g_h1 (sorted order)
// LAYER==2: A = g_h1 (sorted, direct),           Out = g_h2 (sorted order)
#define BM 64
#define BN 64
#define BK 16

template <int KDIM, int NDIM, int LAYER>
__global__ void __launch_bounds__(256)
k_gemm(const float* __restrict__ x_s, const float* __restrict__ x_p,
       const float* __restrict__ W, const float* __restrict__ bias)
{
    const int e    = blockIdx.z;
    const int base = g_off[e];
    const int cnt  = g_off[e + 1] - base;
    const int m0   = blockIdx.y * BM;
    if (m0 >= cnt) return;
    const int n0 = blockIdx.x * BN;

    __shared__ float As[BK][BM];
    __shared__ float Bs[BK][BN];

    const int t = threadIdx.x;
    // A-load role: thread loads a float4 along K for one M-row
    const int lm = t >> 2;             // 0..63
    const int lk = (t & 3) << 2;       // 0,4,8,12
    // B-load role: thread loads a float4 along N for one K-row
    const int bk = t >> 4;             // 0..15
    const int bn = (t & 15) << 2;      // 0..60
    // compute role: 4x4 microtile
    const int ty = t >> 4;             // 0..15 (M dir)
    const int tx = t & 15;             // 0..15 (N dir)

    const float* Wp = W + (size_t)e * KDIM * NDIM + n0;

    const float* arow0 = nullptr;      // k in [0, 512)
    const float* arow1 = nullptr;      // k in [512, 1024)  (layer1 only)
    const bool avalid = (m0 + lm) < cnt;
    if (avalid) {
        if (LAYER == 1) {
            int r = g_perm[base + m0 + lm];
            arow0 = x_p + (size_t)r * L_;          // concat: first L cols = x_p
            arow1 = x_s + (size_t)r * L_;          // next L cols = x_s
        } else {
            arow0 = g_h1 + (size_t)(base + m0 + lm) * KDIM;
        }
    }

    float acc[4][4];
#pragma unroll
    for (int i = 0; i < 4; i++)
#pragma unroll
        for (int j = 0; j < 4; j++) acc[i][j] = 0.f;

    for (int kt = 0; kt < KDIM; kt += BK) {
        float4 a4 = make_float4(0.f, 0.f, 0.f, 0.f);
        if (avalid) {
            int k = kt + lk;
            const float* p;
            if (LAYER == 1) p = (k < L_) ? (arow0 + k) : (arow1 + (k - L_));
            else            p = arow0 + k;
            a4 = *(const float4*)p;
        }
        As[lk + 0][lm] = a4.x;
        As[lk + 1][lm] = a4.y;
        As[lk + 2][lm] = a4.z;
        As[lk + 3][lm] = a4.w;

        *(float4*)&Bs[bk][bn] =
            *(const float4*)(Wp + (size_t)(kt + bk) * NDIM + bn);

        __syncthreads();

#pragma unroll
        for (int k = 0; k < BK; k++) {
            float4 a = *(const float4*)&As[k][ty << 2];
            float4 b = *(const float4*)&Bs[k][tx << 2];
            float av[4] = {a.x, a.y, a.z, a.w};
            float bv[4] = {b.x, b.y, b.z, b.w};
#pragma unroll
            for (int i = 0; i < 4; i++)
#pragma unroll
                for (int j = 0; j < 4; j++)
                    acc[i][j] += av[i] * bv[j];
        }
        __syncthreads();
    }

    float* Out = (LAYER == 1) ? g_h1 : g_h2;
#pragma unroll
    for (int i = 0; i < 4; i++) {
        int rm = m0 + (ty << 2) + i;
        if (rm >= cnt) break;
        size_t orow = (size_t)(base + rm) * NDIM;
#pragma unroll
        for (int j = 0; j < 4; j++) {
            int   n = n0 + (tx << 2) + j;
            float v = acc[i][j] + bias[e * NDIM + n];
            v = (v > 0.f) ? v : expm1f(v);   // jax.nn.elu, alpha=1
            Out[orow + n] = v;
        }
    }
}

// ---------------- layer 3: [B,512] x [512,40] + bias, scatter ----------------
__global__ void __launch_bounds__(64)
k_l3(const float* __restrict__ W3, const float* __restrict__ b3,
     float* __restrict__ out)
{
    const int srow = blockIdx.x;               // sorted row
    int e = 0;
#pragma unroll
    for (int i = 0; i < E_ - 1; i++)
        if (g_off[i + 1] <= srow) e = i + 1;
    const int orig = g_perm[srow];

    __shared__ float h[H2_];
    for (int k = threadIdx.x; k < H2_; k += blockDim.x)
        h[k] = g_h2[(size_t)srow * H2_ + k];
    __syncthreads();

    const int c = threadIdx.x;
    if (c < C_) {
        const float* W = W3 + (size_t)e * H2_ * C_;
        float acc = 0.f;
#pragma unroll 8
        for (int k = 0; k < H2_; k++)
            acc += h[k] * W[k * C_ + c];
        out[(size_t)orig * C_ + c] = acc + b3[e * C_ + c];
    }
}

// ---------------- launch ----------------
extern "C" void kernel_launch(void* const* d_in, const int* in_sizes, int n_in,
                              void* d_out, int out_size)
{
    const float* x_s   = (const float*)d_in[0];
    const float* x_p   = (const float*)d_in[1];
    const float* W1    = (const float*)d_in[2];
    const float* b1    = (const float*)d_in[3];
    const float* W2    = (const float*)d_in[4];
    const float* b2    = (const float*)d_in[5];
    const float* W3    = (const float*)d_in[6];
    const float* b3    = (const float*)d_in[7];
    const int*   label = (const int*)d_in[8];
    (void)in_sizes; (void)n_in;
    float* out = (float*)d_out; (void)out_size;

    k_init<<<1, 32>>>();
    k_hist<<<B_ / 256, 256>>>(label);
    k_scan<<<1, 1>>>();
    k_scatter<<<B_ / 256, 256>>>(label);

    // max M-tiles per expert = B/BM = 64 (covers worst-case skew); empty tiles exit
    dim3 g1(H1_ / BN, B_ / BM, E_);     // (16, 64, 8)
    k_gemm<2 * L_, H1_, 1><<<g1, 256>>>(x_s, x_p, W1, b1);

    dim3 g2(H2_ / BN, B_ / BM, E_);     // (8, 64, 8)
    k_gemm<H1_, H2_, 2><<<g2, 256>>>(x_s, x_p, W2, b2);

    k_l3<<<B_, 64>>>(W3, b3, out);
}